// round 1
// baseline (speedup 1.0000x reference)
#include <cuda_runtime.h>
#include <math.h>

#define D 256
#define BATCH 64
#define NTOK 4096
#define S 8
#define ROWS_BIG (BATCH * NTOK)   // 262144
#define ROWS_SLOT (BATCH * S)     // 512
#define PWARP 64                  // warp-groups per batch in attention pass

// ---------------- scratch (device globals; no allocations allowed) ----------
__device__ float g_xln[(size_t)ROWS_BIG * D];      // 268 MB
__device__ float g_kbuf[(size_t)ROWS_BIG * D];     // 268 MB
__device__ float g_vbuf[(size_t)ROWS_BIG * D];     // 268 MB
__device__ float g_slots[ROWS_SLOT * D];
__device__ float g_sn[ROWS_SLOT * D];
__device__ float g_qbuf[ROWS_SLOT * D];
__device__ float g_upd[ROWS_SLOT * D];
__device__ float g_hbuf[ROWS_SLOT * D];
__device__ float g_gx[ROWS_SLOT * 3 * D];
__device__ float g_gh[ROWS_SLOT * 3 * D];
__device__ float g_pnum[(size_t)BATCH * PWARP * S * D];  // 33.5 MB
__device__ float g_pden[BATCH * PWARP * S];

// ---------------- LayerNorm: one warp per row (D=256) -----------------------
__global__ void ln_rows_kernel(const float* __restrict__ in, float* __restrict__ out,
                               const float* __restrict__ gamma, const float* __restrict__ beta,
                               int nrows)
{
    int gw   = (blockIdx.x * blockDim.x + threadIdx.x) >> 5;
    int lane = threadIdx.x & 31;
    if (gw >= nrows) return;
    const float* row = in + (size_t)gw * D;
    float4 a = *(const float4*)(row + lane * 4);
    float4 b = *(const float4*)(row + 128 + lane * 4);
    float s  = a.x + a.y + a.z + a.w + b.x + b.y + b.z + b.w;
    float s2 = a.x*a.x + a.y*a.y + a.z*a.z + a.w*a.w
             + b.x*b.x + b.y*b.y + b.z*b.z + b.w*b.w;
#pragma unroll
    for (int off = 16; off; off >>= 1) {
        s  += __shfl_xor_sync(0xffffffffu, s,  off);
        s2 += __shfl_xor_sync(0xffffffffu, s2, off);
    }
    float mean = s * (1.0f / 256.0f);
    float var  = s2 * (1.0f / 256.0f) - mean * mean;
    float rstd = rsqrtf(var + 1e-5f);
    float4 g0 = *(const float4*)(gamma + lane * 4);
    float4 g1 = *(const float4*)(gamma + 128 + lane * 4);
    float4 e0 = *(const float4*)(beta + lane * 4);
    float4 e1 = *(const float4*)(beta + 128 + lane * 4);
    float4 o0, o1;
    o0.x = (a.x - mean) * rstd * g0.x + e0.x;
    o0.y = (a.y - mean) * rstd * g0.y + e0.y;
    o0.z = (a.z - mean) * rstd * g0.z + e0.z;
    o0.w = (a.w - mean) * rstd * g0.w + e0.w;
    o1.x = (b.x - mean) * rstd * g1.x + e1.x;
    o1.y = (b.y - mean) * rstd * g1.y + e1.y;
    o1.z = (b.z - mean) * rstd * g1.z + e1.z;
    o1.w = (b.w - mean) * rstd * g1.w + e1.w;
    *(float4*)(out + (size_t)gw * D + lane * 4)       = o0;
    *(float4*)(out + (size_t)gw * D + 128 + lane * 4) = o1;
}

// ---------------- Generic SGEMM: C[M,N] = A[M,K] @ W[N,K]^T + bias ----------
template <int BM, int BN, int BK, int TM, int TN>
__global__ void sgemm_kernel(const float* __restrict__ A, const float* __restrict__ W,
                             const float* __restrict__ bias, float* __restrict__ C,
                             int M, int N, int K, int relu, int accum)
{
    constexpr int THREADS = (BM / TM) * (BN / TN);
    __shared__ float As[BK][BM + 4];
    __shared__ float Ws[BK][BN + 4];
    const int tid  = threadIdx.x;
    const int bm   = blockIdx.y * BM;
    const int bn   = blockIdx.x * BN;
    const int tcol = (tid % (BN / TN)) * TN;
    const int trow = (tid / (BN / TN)) * TM;

    float acc[TM][TN];
#pragma unroll
    for (int i = 0; i < TM; i++)
#pragma unroll
        for (int j = 0; j < TN; j++) acc[i][j] = 0.0f;

    for (int k0 = 0; k0 < K; k0 += BK) {
        constexpr int AL = (BM * BK) / (THREADS * 4);
#pragma unroll
        for (int t = 0; t < AL; t++) {
            int idx = (tid + t * THREADS) * 4;
            int r = idx / BK, c = idx % BK;
            float4 val = *(const float4*)&A[(size_t)(bm + r) * K + k0 + c];
            As[c + 0][r] = val.x; As[c + 1][r] = val.y;
            As[c + 2][r] = val.z; As[c + 3][r] = val.w;
        }
        constexpr int WL = (BN * BK) / (THREADS * 4);
#pragma unroll
        for (int t = 0; t < WL; t++) {
            int idx = (tid + t * THREADS) * 4;
            int r = idx / BK, c = idx % BK;
            float4 val = *(const float4*)&W[(size_t)(bn + r) * K + k0 + c];
            Ws[c + 0][r] = val.x; Ws[c + 1][r] = val.y;
            Ws[c + 2][r] = val.z; Ws[c + 3][r] = val.w;
        }
        __syncthreads();
#pragma unroll
        for (int kk = 0; kk < BK; kk++) {
            float a[TM], b[TN];
#pragma unroll
            for (int i = 0; i < TM; i += 4) {
                float4 t4 = *(const float4*)&As[kk][trow + i];
                a[i] = t4.x; a[i + 1] = t4.y; a[i + 2] = t4.z; a[i + 3] = t4.w;
            }
#pragma unroll
            for (int j = 0; j < TN; j += 4) {
                float4 t4 = *(const float4*)&Ws[kk][tcol + j];
                b[j] = t4.x; b[j + 1] = t4.y; b[j + 2] = t4.z; b[j + 3] = t4.w;
            }
#pragma unroll
            for (int i = 0; i < TM; i++)
#pragma unroll
                for (int j = 0; j < TN; j++) acc[i][j] += a[i] * b[j];
        }
        __syncthreads();
    }

#pragma unroll
    for (int i = 0; i < TM; i++) {
        int r = bm + trow + i;
#pragma unroll
        for (int j = 0; j < TN; j += 4) {
            int c = bn + tcol + j;
            float4 o;
            o.x = acc[i][j + 0] + bias[c + 0];
            o.y = acc[i][j + 1] + bias[c + 1];
            o.z = acc[i][j + 2] + bias[c + 2];
            o.w = acc[i][j + 3] + bias[c + 3];
            if (relu) {
                o.x = fmaxf(o.x, 0.0f); o.y = fmaxf(o.y, 0.0f);
                o.z = fmaxf(o.z, 0.0f); o.w = fmaxf(o.w, 0.0f);
            }
            if (accum) {
                float4 old = *(const float4*)&C[(size_t)r * N + c];
                o.x += old.x; o.y += old.y; o.z += old.z; o.w += old.w;
            }
            *(float4*)&C[(size_t)r * N + c] = o;
        }
    }
}

// ---------------- Fused attention pass ---------------------------------------
// Per token n: dots_i = scale * q_i . k_n, softmax over slots i, a_i += EPS,
// accumulate num_i += a_i * v_n, den_i += a_i.  One warp per token stream.
// Deterministic: per-warp partials, reduced in a separate kernel.
__global__ void attn_pass_kernel(const float* __restrict__ q,
                                 const float* __restrict__ k,
                                 const float* __restrict__ v,
                                 float* __restrict__ pnum,
                                 float* __restrict__ pden)
{
    const int b    = blockIdx.y;
    const int wid  = threadIdx.x >> 5;
    const int lane = threadIdx.x & 31;
    const int wg   = blockIdx.x * 8 + wid;   // 0..63
    const float scale = 0.0625f;             // 256^-0.5

    // q in registers, pre-scaled: qr[i][j] covers element lane*8+j of slot i
    float qr[8][8];
    const float* qb = q + b * S * D;
#pragma unroll
    for (int i = 0; i < 8; i++) {
        float4 q0 = *(const float4*)(qb + i * D + lane * 8);
        float4 q1 = *(const float4*)(qb + i * D + lane * 8 + 4);
        qr[i][0] = q0.x * scale; qr[i][1] = q0.y * scale;
        qr[i][2] = q0.z * scale; qr[i][3] = q0.w * scale;
        qr[i][4] = q1.x * scale; qr[i][5] = q1.y * scale;
        qr[i][6] = q1.z * scale; qr[i][7] = q1.w * scale;
    }

    float acc[8][8];
#pragma unroll
    for (int i = 0; i < 8; i++)
#pragma unroll
        for (int j = 0; j < 8; j++) acc[i][j] = 0.0f;
    float den[8] = {0, 0, 0, 0, 0, 0, 0, 0};

    const size_t base = (size_t)b * NTOK * D;
    const float* kb = k + base;
    const float* vb = v + base;

    int n = wg;
    const float* kp = kb + (size_t)n * D + lane * 8;
    const float* vp = vb + (size_t)n * D + lane * 8;
    float4 k0 = *(const float4*)kp, k1 = *(const float4*)(kp + 4);
    float4 v0 = *(const float4*)vp, v1 = *(const float4*)(vp + 4);

#pragma unroll 1
    for (int t = 0; t < 64; t++) {
        // prefetch next token
        float4 nk0 = k0, nk1 = k1, nv0 = v0, nv1 = v1;
        int nn = n + 64;
        if (t < 63) {
            const float* kq = kb + (size_t)nn * D + lane * 8;
            const float* vq = vb + (size_t)nn * D + lane * 8;
            nk0 = *(const float4*)kq; nk1 = *(const float4*)(kq + 4);
            nv0 = *(const float4*)vq; nv1 = *(const float4*)(vq + 4);
        }

        float kx[8] = {k0.x, k0.y, k0.z, k0.w, k1.x, k1.y, k1.z, k1.w};
        float dot[8];
#pragma unroll
        for (int i = 0; i < 8; i++) {
            float d0 = 0.0f;
#pragma unroll
            for (int j = 0; j < 8; j++) d0 += qr[i][j] * kx[j];
            dot[i] = d0;
        }
#pragma unroll
        for (int off = 16; off; off >>= 1)
#pragma unroll
            for (int i = 0; i < 8; i++)
                dot[i] += __shfl_xor_sync(0xffffffffu, dot[i], off);

        float m = dot[0];
#pragma unroll
        for (int i = 1; i < 8; i++) m = fmaxf(m, dot[i]);
        float e[8]; float ssum = 0.0f;
#pragma unroll
        for (int i = 0; i < 8; i++) { e[i] = __expf(dot[i] - m); ssum += e[i]; }
        float inv = 1.0f / ssum;

        float vx[8] = {v0.x, v0.y, v0.z, v0.w, v1.x, v1.y, v1.z, v1.w};
#pragma unroll
        for (int i = 0; i < 8; i++) {
            float a = e[i] * inv + 1e-8f;
            den[i] += a;
#pragma unroll
            for (int j = 0; j < 8; j++) acc[i][j] += a * vx[j];
        }

        n = nn; k0 = nk0; k1 = nk1; v0 = nv0; v1 = nv1;
    }

    float* pn = pnum + ((size_t)b * PWARP + wg) * S * D;
#pragma unroll
    for (int i = 0; i < 8; i++) {
        *(float4*)(pn + i * D + lane * 8)     = make_float4(acc[i][0], acc[i][1], acc[i][2], acc[i][3]);
        *(float4*)(pn + i * D + lane * 8 + 4) = make_float4(acc[i][4], acc[i][5], acc[i][6], acc[i][7]);
    }
    if (lane == 0) {
#pragma unroll
        for (int i = 0; i < 8; i++) pden[(b * PWARP + wg) * S + i] = den[i];
    }
}

__global__ void attn_reduce_kernel(const float* __restrict__ pnum,
                                   const float* __restrict__ pden,
                                   float* __restrict__ upd)
{
    int idx = blockIdx.x * blockDim.x + threadIdx.x;  // over 64*8*256
    int b = idx >> 11;
    int i = (idx >> 8) & 7;
    float s = 0.0f, d = 0.0f;
#pragma unroll 4
    for (int w = 0; w < PWARP; w++) {
        s += pnum[((size_t)b * PWARP + w) * S * D + (idx & 2047)];
        d += pden[(b * PWARP + w) * S + i];
    }
    upd[idx] = s / d;
}

// ---------------- GRU pointwise (torch gate order r,z,n) ---------------------
__global__ void gru_kernel(const float* __restrict__ gx, const float* __restrict__ gh,
                           float* __restrict__ slots)
{
    int idx = blockIdx.x * blockDim.x + threadIdx.x;  // over 512*256
    int row = idx >> 8, d = idx & 255;
    const float* gxr = gx + row * 3 * D;
    const float* ghr = gh + row * 3 * D;
    float xr = gxr[d], xz = gxr[D + d], xn = gxr[2 * D + d];
    float hr = ghr[d], hz = ghr[D + d], hn = ghr[2 * D + d];
    float r = 1.0f / (1.0f + expf(-(xr + hr)));
    float z = 1.0f / (1.0f + expf(-(xz + hz)));
    float nv = tanhf(xn + r * hn);
    float prev = slots[idx];
    slots[idx] = (1.0f - z) * nv + z * prev;
}

// ---------------- host orchestration ----------------------------------------
extern "C" void kernel_launch(void* const* d_in, const int* in_sizes, int n_in,
                              void* d_out, int out_size)
{
    const float* inputs     = (const float*)d_in[0];
    const float* init_slots = (const float*)d_in[1];
    const float* wq   = (const float*)d_in[2];  const float* bq   = (const float*)d_in[3];
    const float* wk   = (const float*)d_in[4];  const float* bk   = (const float*)d_in[5];
    const float* wv   = (const float*)d_in[6];  const float* bv   = (const float*)d_in[7];
    const float* w_ih = (const float*)d_in[8];  const float* b_ih = (const float*)d_in[9];
    const float* w_hh = (const float*)d_in[10]; const float* b_hh = (const float*)d_in[11];
    const float* w1   = (const float*)d_in[12]; const float* b1   = (const float*)d_in[13];
    const float* w2   = (const float*)d_in[14]; const float* b2   = (const float*)d_in[15];
    const float* gin  = (const float*)d_in[16]; const float* bin  = (const float*)d_in[17];
    const float* gsl  = (const float*)d_in[18]; const float* bsl  = (const float*)d_in[19];
    const float* gff  = (const float*)d_in[20]; const float* bff  = (const float*)d_in[21];

    float *xln, *kbuf, *vbuf, *slots, *sn, *qb, *upd, *hb, *gx, *gh, *pnum, *pden;
    cudaGetSymbolAddress((void**)&xln,   g_xln);
    cudaGetSymbolAddress((void**)&kbuf,  g_kbuf);
    cudaGetSymbolAddress((void**)&vbuf,  g_vbuf);
    cudaGetSymbolAddress((void**)&slots, g_slots);
    cudaGetSymbolAddress((void**)&sn,    g_sn);
    cudaGetSymbolAddress((void**)&qb,    g_qbuf);
    cudaGetSymbolAddress((void**)&upd,   g_upd);
    cudaGetSymbolAddress((void**)&hb,    g_hbuf);
    cudaGetSymbolAddress((void**)&gx,    g_gx);
    cudaGetSymbolAddress((void**)&gh,    g_gh);
    cudaGetSymbolAddress((void**)&pnum,  g_pnum);
    cudaGetSymbolAddress((void**)&pden,  g_pden);

    // prologue: slots <- init, x_ln = LN(inputs), k/v projections
    cudaMemcpyAsync(slots, init_slots, (size_t)ROWS_SLOT * D * sizeof(float),
                    cudaMemcpyDeviceToDevice);
    ln_rows_kernel<<<ROWS_BIG / 8, 256>>>(inputs, xln, gin, bin, ROWS_BIG);

    dim3 gbig(D / 128, ROWS_BIG / 128);
    sgemm_kernel<128, 128, 16, 8, 8><<<gbig, 256>>>(xln, wk, bk, kbuf, ROWS_BIG, D, D, 0, 0);
    sgemm_kernel<128, 128, 16, 8, 8><<<gbig, 256>>>(xln, wv, bv, vbuf, ROWS_BIG, D, D, 0, 0);

    for (int it = 0; it < 3; it++) {
        // q = LN(slots) @ wq^T + bq
        ln_rows_kernel<<<ROWS_SLOT / 8, 256>>>(slots, sn, gsl, bsl, ROWS_SLOT);
        sgemm_kernel<64, 64, 16, 4, 4><<<dim3(D / 64, ROWS_SLOT / 64), 256>>>(
            sn, wq, bq, qb, ROWS_SLOT, D, D, 0, 0);
        // fused attention (single pass over k,v)
        attn_pass_kernel<<<dim3(8, BATCH), 256>>>(qb, kbuf, vbuf, pnum, pden);
        attn_reduce_kernel<<<(BATCH * S * D) / 256, 256>>>(pnum, pden, upd);
        // GRU
        sgemm_kernel<64, 64, 16, 4, 4><<<dim3(3 * D / 64, ROWS_SLOT / 64), 256>>>(
            upd, w_ih, b_ih, gx, ROWS_SLOT, 3 * D, D, 0, 0);
        sgemm_kernel<64, 64, 16, 4, 4><<<dim3(3 * D / 64, ROWS_SLOT / 64), 256>>>(
            slots, w_hh, b_hh, gh, ROWS_SLOT, 3 * D, D, 0, 0);
        gru_kernel<<<(ROWS_SLOT * D) / 256, 256>>>(gx, gh, slots);
        // residual MLP
        ln_rows_kernel<<<ROWS_SLOT / 8, 256>>>(slots, sn, gff, bff, ROWS_SLOT);
        sgemm_kernel<64, 64, 16, 4, 4><<<dim3(D / 64, ROWS_SLOT / 64), 256>>>(
            sn, w1, b1, hb, ROWS_SLOT, D, D, 1, 0);
        sgemm_kernel<64, 64, 16, 4, 4><<<dim3(D / 64, ROWS_SLOT / 64), 256>>>(
            hb, w2, b2, slots, ROWS_SLOT, D, D, 0, 1);
    }

    cudaMemcpyAsync(d_out, slots, (size_t)ROWS_SLOT * D * sizeof(float),
                    cudaMemcpyDeviceToDevice);
}

// round 3
// speedup vs baseline: 2.2554x; 2.2554x over previous
#include <cuda_runtime.h>
#include <cuda_bf16.h>
#include <math.h>
#include <stdint.h>

#define D 256
#define BATCH 64
#define NTOK 4096
#define S 8
#define ROWS_BIG (BATCH * NTOK)   // 262144
#define ROWS_SLOT (BATCH * S)     // 512
#define PWARP 64

// ---------------- scratch (device globals; no allocations allowed) ----------
__device__ __nv_bfloat16 g_xln16[(size_t)ROWS_BIG * D];   // 134 MB
__device__ __nv_bfloat16 g_k16[(size_t)ROWS_BIG * D];     // 134 MB
__device__ __nv_bfloat16 g_v16[(size_t)ROWS_BIG * D];     // 134 MB
__device__ __nv_bfloat16 g_w16[2 * D * D];                // concat(Wk, Wv) [512,256]
__device__ float g_bias[2 * D];                           // concat(bk, bv)
__device__ float g_slots[ROWS_SLOT * D];
__device__ float g_sn[ROWS_SLOT * D];
__device__ float g_qbuf[ROWS_SLOT * D];
__device__ float g_upd[ROWS_SLOT * D];
__device__ float g_hbuf[ROWS_SLOT * D];
__device__ float g_gx[ROWS_SLOT * 3 * D];
__device__ float g_gh[ROWS_SLOT * 3 * D];
__device__ float g_pnum[(size_t)BATCH * PWARP * S * D];   // 33.5 MB
__device__ float g_pden[BATCH * PWARP * S];

// ---------------- PTX helpers (arch-agnostic: sm_80+ features only) ----------
__device__ __forceinline__ uint32_t smem_u32(const void* p) {
    uint32_t a;
    asm("{ .reg .u64 t; cvta.to.shared.u64 t, %1; cvt.u32.u64 %0, t; }" : "=r"(a) : "l"(p));
    return a;
}
__device__ __forceinline__ void cpasync16(uint32_t saddr, const void* g) {
    asm volatile("cp.async.cg.shared.global [%0], [%1], 16;" :: "r"(saddr), "l"(g));
}
#define CP_COMMIT() asm volatile("cp.async.commit_group;" ::: "memory")
#define CP_WAIT(n)  asm volatile("cp.async.wait_group %0;" :: "n"(n) : "memory")

__device__ __forceinline__ void ldsm_x4(uint32_t& r0, uint32_t& r1, uint32_t& r2, uint32_t& r3,
                                        uint32_t addr) {
    asm volatile("ldmatrix.sync.aligned.m8n8.x4.shared.b16 {%0,%1,%2,%3}, [%4];"
                 : "=r"(r0), "=r"(r1), "=r"(r2), "=r"(r3) : "r"(addr));
}
__device__ __forceinline__ void mma16816(float* d, const uint32_t* a, const uint32_t* b) {
    asm volatile("mma.sync.aligned.m16n8k16.row.col.f32.bf16.bf16.f32 "
                 "{%0,%1,%2,%3}, {%4,%5,%6,%7}, {%8,%9}, {%0,%1,%2,%3};"
                 : "+f"(d[0]), "+f"(d[1]), "+f"(d[2]), "+f"(d[3])
                 : "r"(a[0]), "r"(a[1]), "r"(a[2]), "r"(a[3]), "r"(b[0]), "r"(b[1]));
}
__device__ __forceinline__ float2 bf2f(uint32_t u) {
    __nv_bfloat162 h = *reinterpret_cast<__nv_bfloat162*>(&u);
    return __bfloat1622float2(h);
}

// ---------------- weights fp32 -> bf16 (concat layout) -----------------------
__global__ void conv_w_kernel(const float* __restrict__ wk, const float* __restrict__ wv,
                              const float* __restrict__ bk, const float* __restrict__ bv,
                              __nv_bfloat16* __restrict__ w16, float* __restrict__ bias)
{
    int i = blockIdx.x * 256 + threadIdx.x;   // 0..65535
    w16[i]             = __float2bfloat16(wk[i]);
    w16[i + D * D]     = __float2bfloat16(wv[i]);
    if (i < D) { bias[i] = bk[i]; bias[i + D] = bv[i]; }
}

// ---------------- LayerNorm fp32 -> fp32 (slot rows) -------------------------
__global__ void ln_rows_kernel(const float* __restrict__ in, float* __restrict__ out,
                               const float* __restrict__ gamma, const float* __restrict__ beta,
                               int nrows)
{
    int gw   = (blockIdx.x * blockDim.x + threadIdx.x) >> 5;
    int lane = threadIdx.x & 31;
    if (gw >= nrows) return;
    const float* row = in + (size_t)gw * D;
    float4 a = *(const float4*)(row + lane * 4);
    float4 b = *(const float4*)(row + 128 + lane * 4);
    float s  = a.x + a.y + a.z + a.w + b.x + b.y + b.z + b.w;
    float s2 = a.x*a.x + a.y*a.y + a.z*a.z + a.w*a.w
             + b.x*b.x + b.y*b.y + b.z*b.z + b.w*b.w;
#pragma unroll
    for (int off = 16; off; off >>= 1) {
        s  += __shfl_xor_sync(0xffffffffu, s,  off);
        s2 += __shfl_xor_sync(0xffffffffu, s2, off);
    }
    float mean = s * (1.0f / 256.0f);
    float var  = s2 * (1.0f / 256.0f) - mean * mean;
    float rstd = rsqrtf(var + 1e-5f);
    float4 g0 = *(const float4*)(gamma + lane * 4);
    float4 g1 = *(const float4*)(gamma + 128 + lane * 4);
    float4 e0 = *(const float4*)(beta + lane * 4);
    float4 e1 = *(const float4*)(beta + 128 + lane * 4);
    float4 o0, o1;
    o0.x = (a.x - mean) * rstd * g0.x + e0.x;
    o0.y = (a.y - mean) * rstd * g0.y + e0.y;
    o0.z = (a.z - mean) * rstd * g0.z + e0.z;
    o0.w = (a.w - mean) * rstd * g0.w + e0.w;
    o1.x = (b.x - mean) * rstd * g1.x + e1.x;
    o1.y = (b.y - mean) * rstd * g1.y + e1.y;
    o1.z = (b.z - mean) * rstd * g1.z + e1.z;
    o1.w = (b.w - mean) * rstd * g1.w + e1.w;
    *(float4*)(out + (size_t)gw * D + lane * 4)       = o0;
    *(float4*)(out + (size_t)gw * D + 128 + lane * 4) = o1;
}

// ---------------- LayerNorm fp32 -> bf16 (big input) -------------------------
__global__ void ln_rows_bf16_kernel(const float* __restrict__ in, __nv_bfloat16* __restrict__ out,
                                    const float* __restrict__ gamma, const float* __restrict__ beta)
{
    int gw   = (blockIdx.x * blockDim.x + threadIdx.x) >> 5;
    int lane = threadIdx.x & 31;
    const float* row = in + (size_t)gw * D;
    float4 a = *(const float4*)(row + lane * 4);
    float4 b = *(const float4*)(row + 128 + lane * 4);
    float s  = a.x + a.y + a.z + a.w + b.x + b.y + b.z + b.w;
    float s2 = a.x*a.x + a.y*a.y + a.z*a.z + a.w*a.w
             + b.x*b.x + b.y*b.y + b.z*b.z + b.w*b.w;
#pragma unroll
    for (int off = 16; off; off >>= 1) {
        s  += __shfl_xor_sync(0xffffffffu, s,  off);
        s2 += __shfl_xor_sync(0xffffffffu, s2, off);
    }
    float mean = s * (1.0f / 256.0f);
    float var  = s2 * (1.0f / 256.0f) - mean * mean;
    float rstd = rsqrtf(var + 1e-5f);
    float4 g0 = *(const float4*)(gamma + lane * 4);
    float4 g1 = *(const float4*)(gamma + 128 + lane * 4);
    float4 e0 = *(const float4*)(beta + lane * 4);
    float4 e1 = *(const float4*)(beta + 128 + lane * 4);
    __nv_bfloat162 p[4];
    p[0] = __float22bfloat162_rn(make_float2((a.x - mean) * rstd * g0.x + e0.x,
                                             (a.y - mean) * rstd * g0.y + e0.y));
    p[1] = __float22bfloat162_rn(make_float2((a.z - mean) * rstd * g0.z + e0.z,
                                             (a.w - mean) * rstd * g0.w + e0.w));
    p[2] = __float22bfloat162_rn(make_float2((b.x - mean) * rstd * g1.x + e1.x,
                                             (b.y - mean) * rstd * g1.y + e1.y));
    p[3] = __float22bfloat162_rn(make_float2((b.z - mean) * rstd * g1.z + e1.z,
                                             (b.w - mean) * rstd * g1.w + e1.w));
    __nv_bfloat16* o = out + (size_t)gw * D;
    *(uint2*)(o + lane * 4)       = make_uint2(*(uint32_t*)&p[0], *(uint32_t*)&p[1]);
    *(uint2*)(o + 128 + lane * 4) = make_uint2(*(uint32_t*)&p[2], *(uint32_t*)&p[3]);
}

// ---------------- KV projection: bf16 mma.sync GEMM --------------------------
// C[262144, 512] = A[262144,256] @ W[512,256]^T ; cols 0-255 -> K, 256-511 -> V
// Tiles: CTA 128x128, K-block 64, double-buffered cp.async, 8 warps (32x64 each)
#define BMT 128
#define BNT 128
#define BKT 64
#define KV_STAGE 16384                 // bytes per As or Bs stage
#define KV_SMEM  (4 * KV_STAGE)        // 64 KB

__global__ void __launch_bounds__(256) kv_mma_kernel(
    const __nv_bfloat16* __restrict__ A,
    const __nv_bfloat16* __restrict__ W,
    const float* __restrict__ bias,
    __nv_bfloat16* __restrict__ Kout,
    __nv_bfloat16* __restrict__ Vout)
{
    extern __shared__ char smem[];
    const int tid  = threadIdx.x;
    const int lane = tid & 31;
    const int wid  = tid >> 5;
    const int wm   = wid >> 1;           // 0..3 -> 32-row slab
    const int wn   = wid & 1;            // 0..1 -> 64-col slab
    const int bm   = blockIdx.y * BMT;
    const int bn   = blockIdx.x * BNT;
    const uint32_t sb = smem_u32(smem);

    const char* Ag = (const char*)A + (size_t)bm * 512;   // 256 bf16 = 512 B/row
    const char* Wg = (const char*)W + (size_t)bn * 512;

    float acc[2][8][4];
#pragma unroll
    for (int mi = 0; mi < 2; mi++)
#pragma unroll
        for (int nj = 0; nj < 8; nj++)
#pragma unroll
            for (int x = 0; x < 4; x++) acc[mi][nj][x] = 0.0f;

    // stage loader: A tile 128x64 bf16 (128 B/row), W tile 128x64
#define LOAD_STAGE(kb, st) do {                                               \
        uint32_t abase = sb + (st) * 2 * KV_STAGE;                            \
        uint32_t bbase = abase + KV_STAGE;                                    \
        const char* ag = Ag + (kb) * 128;                                     \
        const char* wg = Wg + (kb) * 128;                                     \
        _Pragma("unroll")                                                     \
        for (int i = 0; i < 4; i++) {                                         \
            int ci = tid + i * 256;                                           \
            int r = ci >> 3, c = ci & 7;                                      \
            cpasync16(abase + r * 128 + ((c ^ (r & 7)) * 16),                 \
                      ag + (size_t)r * 512 + c * 16);                         \
        }                                                                     \
        _Pragma("unroll")                                                     \
        for (int i = 0; i < 4; i++) {                                         \
            int ci = tid + i * 256;                                           \
            int r = ci >> 3, c = ci & 7;                                      \
            cpasync16(bbase + r * 128 + ((c ^ (r & 7)) * 16),                 \
                      wg + (size_t)r * 512 + c * 16);                         \
        }                                                                     \
        CP_COMMIT();                                                          \
    } while (0)

    LOAD_STAGE(0, 0);

#pragma unroll 1
    for (int kb = 0; kb < 4; kb++) {
        if (kb < 3) { LOAD_STAGE(kb + 1, (kb + 1) & 1); CP_WAIT(1); }
        else        { CP_WAIT(0); }
        __syncthreads();

        uint32_t abase = sb + (kb & 1) * 2 * KV_STAGE;
        uint32_t bbase = abase + KV_STAGE;
#pragma unroll
        for (int ks = 0; ks < 4; ks++) {
            uint32_t afr[2][4];
#pragma unroll
            for (int mi = 0; mi < 2; mi++) {
                int row   = wm * 32 + mi * 16 + (lane & 15);
                int chunk = (ks * 2 + (lane >> 4)) ^ (row & 7);
                ldsm_x4(afr[mi][0], afr[mi][1], afr[mi][2], afr[mi][3],
                        abase + row * 128 + chunk * 16);
            }
            uint32_t bfr[8][2];
#pragma unroll
            for (int njp = 0; njp < 4; njp++) {
                int row   = wn * 64 + njp * 16 + ((lane >> 4) & 1) * 8 + (lane & 7);
                int chunk = (ks * 2 + ((lane >> 3) & 1)) ^ (row & 7);
                uint32_t r0, r1, r2, r3;
                ldsm_x4(r0, r1, r2, r3, bbase + row * 128 + chunk * 16);
                bfr[njp * 2][0]     = r0; bfr[njp * 2][1]     = r1;
                bfr[njp * 2 + 1][0] = r2; bfr[njp * 2 + 1][1] = r3;
            }
#pragma unroll
            for (int mi = 0; mi < 2; mi++)
#pragma unroll
                for (int nj = 0; nj < 8; nj++)
                    mma16816(acc[mi][nj], afr[mi], bfr[nj]);
        }
        __syncthreads();
    }

    // epilogue: + bias, -> bf16, route to K or V
    __nv_bfloat16* outp;
    int cb;
    if (bn < 256) { outp = Kout; cb = bn; } else { outp = Vout; cb = bn - 256; }
#pragma unroll
    for (int mi = 0; mi < 2; mi++) {
        int r0 = bm + wm * 32 + mi * 16 + (lane >> 2);
#pragma unroll
        for (int nj = 0; nj < 8; nj++) {
            int ncol = wn * 64 + nj * 8 + (lane & 3) * 2;
            float2 bs = *(const float2*)&bias[bn + ncol];
            __nv_bfloat162 lo = __float22bfloat162_rn(
                make_float2(acc[mi][nj][0] + bs.x, acc[mi][nj][1] + bs.y));
            __nv_bfloat162 hi = __float22bfloat162_rn(
                make_float2(acc[mi][nj][2] + bs.x, acc[mi][nj][3] + bs.y));
            *(__nv_bfloat162*)(outp + (size_t)r0 * D + cb + ncol)       = lo;
            *(__nv_bfloat162*)(outp + (size_t)(r0 + 8) * D + cb + ncol) = hi;
        }
    }
#undef LOAD_STAGE
}

// ---------------- Small fp32 SGEMM: C[M,N] = A[M,K] @ W[N,K]^T + bias --------
template <int BM, int BN, int BK, int TM, int TN>
__global__ void sgemm_kernel(const float* __restrict__ A, const float* __restrict__ W,
                             const float* __restrict__ bias, float* __restrict__ C,
                             int M, int N, int K, int relu, int accum)
{
    constexpr int THREADS = (BM / TM) * (BN / TN);
    __shared__ float As[BK][BM + 4];
    __shared__ float Ws[BK][BN + 4];
    const int tid  = threadIdx.x;
    const int bm   = blockIdx.y * BM;
    const int bn   = blockIdx.x * BN;
    const int tcol = (tid % (BN / TN)) * TN;
    const int trow = (tid / (BN / TN)) * TM;

    float acc[TM][TN];
#pragma unroll
    for (int i = 0; i < TM; i++)
#pragma unroll
        for (int j = 0; j < TN; j++) acc[i][j] = 0.0f;

    for (int k0 = 0; k0 < K; k0 += BK) {
        constexpr int AL = (BM * BK) / (THREADS * 4);
#pragma unroll
        for (int t = 0; t < AL; t++) {
            int idx = (tid + t * THREADS) * 4;
            int r = idx / BK, c = idx % BK;
            float4 val = *(const float4*)&A[(size_t)(bm + r) * K + k0 + c];
            As[c + 0][r] = val.x; As[c + 1][r] = val.y;
            As[c + 2][r] = val.z; As[c + 3][r] = val.w;
        }
        constexpr int WL = (BN * BK) / (THREADS * 4);
#pragma unroll
        for (int t = 0; t < WL; t++) {
            int idx = (tid + t * THREADS) * 4;
            int r = idx / BK, c = idx % BK;
            float4 val = *(const float4*)&W[(size_t)(bn + r) * K + k0 + c];
            Ws[c + 0][r] = val.x; Ws[c + 1][r] = val.y;
            Ws[c + 2][r] = val.z; Ws[c + 3][r] = val.w;
        }
        __syncthreads();
#pragma unroll
        for (int kk = 0; kk < BK; kk++) {
            float a[TM], b[TN];
#pragma unroll
            for (int i = 0; i < TM; i += 4) {
                float4 t4 = *(const float4*)&As[kk][trow + i];
                a[i] = t4.x; a[i + 1] = t4.y; a[i + 2] = t4.z; a[i + 3] = t4.w;
            }
#pragma unroll
            for (int j = 0; j < TN; j += 4) {
                float4 t4 = *(const float4*)&Ws[kk][tcol + j];
                b[j] = t4.x; b[j + 1] = t4.y; b[j + 2] = t4.z; b[j + 3] = t4.w;
            }
#pragma unroll
            for (int i = 0; i < TM; i++)
#pragma unroll
                for (int j = 0; j < TN; j++) acc[i][j] += a[i] * b[j];
        }
        __syncthreads();
    }

#pragma unroll
    for (int i = 0; i < TM; i++) {
        int r = bm + trow + i;
#pragma unroll
        for (int j = 0; j < TN; j += 4) {
            int c = bn + tcol + j;
            float4 o;
            o.x = acc[i][j + 0] + bias[c + 0];
            o.y = acc[i][j + 1] + bias[c + 1];
            o.z = acc[i][j + 2] + bias[c + 2];
            o.w = acc[i][j + 3] + bias[c + 3];
            if (relu) {
                o.x = fmaxf(o.x, 0.0f); o.y = fmaxf(o.y, 0.0f);
                o.z = fmaxf(o.z, 0.0f); o.w = fmaxf(o.w, 0.0f);
            }
            if (accum) {
                float4 old = *(const float4*)&C[(size_t)r * N + c];
                o.x += old.x; o.y += old.y; o.z += old.z; o.w += old.w;
            }
            *(float4*)&C[(size_t)r * N + c] = o;
        }
    }
}

// ---------------- Fused attention pass (bf16 k/v) ----------------------------
__global__ void attn_pass_kernel(const float* __restrict__ q,
                                 const __nv_bfloat16* __restrict__ k,
                                 const __nv_bfloat16* __restrict__ v,
                                 float* __restrict__ pnum,
                                 float* __restrict__ pden)
{
    const int b    = blockIdx.y;
    const int wid  = threadIdx.x >> 5;
    const int lane = threadIdx.x & 31;
    const int wg   = blockIdx.x * 8 + wid;   // 0..63
    const float scale = 0.0625f;

    float qr[8][8];
    const float* qb = q + b * S * D;
#pragma unroll
    for (int i = 0; i < 8; i++) {
        float4 q0 = *(const float4*)(qb + i * D + lane * 8);
        float4 q1 = *(const float4*)(qb + i * D + lane * 8 + 4);
        qr[i][0] = q0.x * scale; qr[i][1] = q0.y * scale;
        qr[i][2] = q0.z * scale; qr[i][3] = q0.w * scale;
        qr[i][4] = q1.x * scale; qr[i][5] = q1.y * scale;
        qr[i][6] = q1.z * scale; qr[i][7] = q1.w * scale;
    }

    float acc[8][8];
#pragma unroll
    for (int i = 0; i < 8; i++)
#pragma unroll
        for (int j = 0; j < 8; j++) acc[i][j] = 0.0f;
    float den[8] = {0, 0, 0, 0, 0, 0, 0, 0};

    const size_t base = (size_t)b * NTOK * D;
    const __nv_bfloat16* kb = k + base;
    const __nv_bfloat16* vb = v + base;

    int n = wg;
    uint4 ku = *(const uint4*)(kb + (size_t)n * D + lane * 8);
    uint4 vu = *(const uint4*)(vb + (size_t)n * D + lane * 8);

#pragma unroll 1
    for (int t = 0; t < 64; t++) {
        uint4 nku = ku, nvu = vu;
        int nn = n + 64;
        if (t < 63) {
            nku = *(const uint4*)(kb + (size_t)nn * D + lane * 8);
            nvu = *(const uint4*)(vb + (size_t)nn * D + lane * 8);
        }

        float kx[8];
        { float2 f;
          f = bf2f(ku.x); kx[0] = f.x; kx[1] = f.y;
          f = bf2f(ku.y); kx[2] = f.x; kx[3] = f.y;
          f = bf2f(ku.z); kx[4] = f.x; kx[5] = f.y;
          f = bf2f(ku.w); kx[6] = f.x; kx[7] = f.y; }

        float dot[8];
#pragma unroll
        for (int i = 0; i < 8; i++) {
            float d0 = 0.0f;
#pragma unroll
            for (int j = 0; j < 8; j++) d0 += qr[i][j] * kx[j];
            dot[i] = d0;
        }
#pragma unroll
        for (int off = 16; off; off >>= 1)
#pragma unroll
            for (int i = 0; i < 8; i++)
                dot[i] += __shfl_xor_sync(0xffffffffu, dot[i], off);

        float m = dot[0];
#pragma unroll
        for (int i = 1; i < 8; i++) m = fmaxf(m, dot[i]);
        float e[8]; float ssum = 0.0f;
#pragma unroll
        for (int i = 0; i < 8; i++) { e[i] = __expf(dot[i] - m); ssum += e[i]; }
        float inv = 1.0f / ssum;

        float vx[8];
        { float2 f;
          f = bf2f(vu.x); vx[0] = f.x; vx[1] = f.y;
          f = bf2f(vu.y); vx[2] = f.x; vx[3] = f.y;
          f = bf2f(vu.z); vx[4] = f.x; vx[5] = f.y;
          f = bf2f(vu.w); vx[6] = f.x; vx[7] = f.y; }
#pragma unroll
        for (int i = 0; i < 8; i++) {
            float a = e[i] * inv + 1e-8f;
            den[i] += a;
#pragma unroll
            for (int j = 0; j < 8; j++) acc[i][j] += a * vx[j];
        }

        n = nn; ku = nku; vu = nvu;
    }

    float* pn = pnum + ((size_t)b * PWARP + wg) * S * D;
#pragma unroll
    for (int i = 0; i < 8; i++) {
        *(float4*)(pn + i * D + lane * 8)     = make_float4(acc[i][0], acc[i][1], acc[i][2], acc[i][3]);
        *(float4*)(pn + i * D + lane * 8 + 4) = make_float4(acc[i][4], acc[i][5], acc[i][6], acc[i][7]);
    }
    if (lane == 0) {
#pragma unroll
        for (int i = 0; i < 8; i++) pden[(b * PWARP + wg) * S + i] = den[i];
    }
}

__global__ void attn_reduce_kernel(const float* __restrict__ pnum,
                                   const float* __restrict__ pden,
                                   float* __restrict__ upd)
{
    int idx = blockIdx.x * blockDim.x + threadIdx.x;  // over 64*8*256
    int b = idx >> 11;
    int i = (idx >> 8) & 7;
    float s = 0.0f, d = 0.0f;
#pragma unroll 4
    for (int w = 0; w < PWARP; w++) {
        s += pnum[((size_t)b * PWARP + w) * S * D + (idx & 2047)];
        d += pden[(b * PWARP + w) * S + i];
    }
    upd[idx] = s / d;
}

// ---------------- GRU pointwise (torch gate order r,z,n) ---------------------
__global__ void gru_kernel(const float* __restrict__ gx, const float* __restrict__ gh,
                           float* __restrict__ slots)
{
    int idx = blockIdx.x * blockDim.x + threadIdx.x;  // over 512*256
    int row = idx >> 8, d = idx & 255;
    const float* gxr = gx + row * 3 * D;
    const float* ghr = gh + row * 3 * D;
    float xr = gxr[d], xz = gxr[D + d], xn = gxr[2 * D + d];
    float hr = ghr[d], hz = ghr[D + d], hn = ghr[2 * D + d];
    float r = 1.0f / (1.0f + expf(-(xr + hr)));
    float z = 1.0f / (1.0f + expf(-(xz + hz)));
    float nv = tanhf(xn + r * hn);
    float prev = slots[idx];
    slots[idx] = (1.0f - z) * nv + z * prev;
}

// ---------------- host orchestration ----------------------------------------
extern "C" void kernel_launch(void* const* d_in, const int* in_sizes, int n_in,
                              void* d_out, int out_size)
{
    const float* inputs     = (const float*)d_in[0];
    const float* init_slots = (const float*)d_in[1];
    const float* wq   = (const float*)d_in[2];  const float* bq   = (const float*)d_in[3];
    const float* wk   = (const float*)d_in[4];  const float* bk   = (const float*)d_in[5];
    const float* wv   = (const float*)d_in[6];  const float* bv   = (const float*)d_in[7];
    const float* w_ih = (const float*)d_in[8];  const float* b_ih = (const float*)d_in[9];
    const float* w_hh = (const float*)d_in[10]; const float* b_hh = (const float*)d_in[11];
    const float* w1   = (const float*)d_in[12]; const float* b1   = (const float*)d_in[13];
    const float* w2   = (const float*)d_in[14]; const float* b2   = (const float*)d_in[15];
    const float* gin  = (const float*)d_in[16]; const float* bin  = (const float*)d_in[17];
    const float* gsl  = (const float*)d_in[18]; const float* bsl  = (const float*)d_in[19];
    const float* gff  = (const float*)d_in[20]; const float* bff  = (const float*)d_in[21];

    __nv_bfloat16 *xln16, *k16, *v16, *w16;
    float *bias, *slots, *sn, *qb, *upd, *hb, *gx, *gh, *pnum, *pden;
    cudaGetSymbolAddress((void**)&xln16, g_xln16);
    cudaGetSymbolAddress((void**)&k16,   g_k16);
    cudaGetSymbolAddress((void**)&v16,   g_v16);
    cudaGetSymbolAddress((void**)&w16,   g_w16);
    cudaGetSymbolAddress((void**)&bias,  g_bias);
    cudaGetSymbolAddress((void**)&slots, g_slots);
    cudaGetSymbolAddress((void**)&sn,    g_sn);
    cudaGetSymbolAddress((void**)&qb,    g_qbuf);
    cudaGetSymbolAddress((void**)&upd,   g_upd);
    cudaGetSymbolAddress((void**)&hb,    g_hbuf);
    cudaGetSymbolAddress((void**)&gx,    g_gx);
    cudaGetSymbolAddress((void**)&gh,    g_gh);
    cudaGetSymbolAddress((void**)&pnum,  g_pnum);
    cudaGetSymbolAddress((void**)&pden,  g_pden);

    cudaFuncSetAttribute(kv_mma_kernel, cudaFuncAttributeMaxDynamicSharedMemorySize, KV_SMEM);

    // prologue
    cudaMemcpyAsync(slots, init_slots, (size_t)ROWS_SLOT * D * sizeof(float),
                    cudaMemcpyDeviceToDevice);
    conv_w_kernel<<<D * D / 256, 256>>>(wk, wv, bk, bv, w16, bias);
    ln_rows_bf16_kernel<<<ROWS_BIG / 8, 256>>>(inputs, xln16, gin, bin);
    kv_mma_kernel<<<dim3(4, ROWS_BIG / BMT), 256, KV_SMEM>>>(xln16, w16, bias, k16, v16);

    for (int it = 0; it < 3; it++) {
        ln_rows_kernel<<<ROWS_SLOT / 8, 256>>>(slots, sn, gsl, bsl, ROWS_SLOT);
        sgemm_kernel<64, 64, 16, 4, 4><<<dim3(D / 64, ROWS_SLOT / 64), 256>>>(
            sn, wq, bq, qb, ROWS_SLOT, D, D, 0, 0);
        attn_pass_kernel<<<dim3(8, BATCH), 256>>>(qb, k16, v16, pnum, pden);
        attn_reduce_kernel<<<(BATCH * S * D) / 256, 256>>>(pnum, pden, upd);
        sgemm_kernel<64, 64, 16, 4, 4><<<dim3(3 * D / 64, ROWS_SLOT / 64), 256>>>(
            upd, w_ih, b_ih, gx, ROWS_SLOT, 3 * D, D, 0, 0);
        sgemm_kernel<64, 64, 16, 4, 4><<<dim3(3 * D / 64, ROWS_SLOT / 64), 256>>>(
            slots, w_hh, b_hh, gh, ROWS_SLOT, 3 * D, D, 0, 0);
        gru_kernel<<<(ROWS_SLOT * D) / 256, 256>>>(gx, gh, slots);
        ln_rows_kernel<<<ROWS_SLOT / 8, 256>>>(slots, sn, gff, bff, ROWS_SLOT);
        sgemm_kernel<64, 64, 16, 4, 4><<<dim3(D / 64, ROWS_SLOT / 64), 256>>>(
            sn, w1, b1, hb, ROWS_SLOT, D, D, 1, 0);
        sgemm_kernel<64, 64, 16, 4, 4><<<dim3(D / 64, ROWS_SLOT / 64), 256>>>(
            hb, w2, b2, slots, ROWS_SLOT, D, D, 0, 1);
    }

    cudaMemcpyAsync(d_out, slots, (size_t)ROWS_SLOT * D * sizeof(float),
                    cudaMemcpyDeviceToDevice);
}